// round 7
// baseline (speedup 1.0000x reference)
#include <cuda_runtime.h>
#include <cuda_bf16.h>
#include <cstdint>
#include <cstddef>

// ---------------- problem constants ----------------
#define MROWS 8192
#define FDIM  1024
#define HDIM  512
#define GDIM  2048
#define KFUSE 1536
#define DSTEPS 8

// ---------------- GEMM tile config ----------------
#define BM 128
#define BN 128
#define BK 32                 // bf16 elems per chunk (64 bytes per row)
#define STAGES 3
#define NTHR 256
#define A_TILE_B (BM*64)      // 8192
#define W_TILE_B (BN*64)      // 8192
#define STAGE_B (2*A_TILE_B + 2*W_TILE_B)    // 32768
#define SMEM_TOTAL (STAGES*STAGE_B)          // 98304
#define GRANULES (STAGE_B/16)                // 2048

// ---------------- scratch (device globals) ----------------
__device__ __align__(256) __nv_bfloat16 g_out_hi[(size_t)MROWS*FDIM];   // x-part of A (cls output)
__device__ __align__(256) __nv_bfloat16 g_out_lo[(size_t)MROWS*FDIM];
__device__ __align__(256) __nv_bfloat16 g_h_hi[2][(size_t)MROWS*HDIM];  // double-buffered h
__device__ __align__(256) __nv_bfloat16 g_h_lo[2][(size_t)MROWS*HDIM];
__device__ __align__(256) __nv_bfloat16 g_wg_hi[(size_t)GDIM*KFUSE];    // gate-permuted fused W
__device__ __align__(256) __nv_bfloat16 g_wg_lo[(size_t)GDIM*KFUSE];
__device__ __align__(256) __nv_bfloat16 g_wc_hi[(size_t)FDIM*HDIM];
__device__ __align__(256) __nv_bfloat16 g_wc_lo[(size_t)FDIM*HDIM];
__device__ __align__(256) float g_biasg[GDIM];                          // permuted b_ih+b_hh
__device__ __align__(256) float g_c[(size_t)MROWS*HDIM];

// ---------------- helpers ----------------
__device__ __forceinline__ uint32_t smem_u32(const void* p) {
    uint32_t a;
    asm("{ .reg .u64 t; cvta.to.shared.u64 t, %1; cvt.u32.u64 %0, t; }" : "=r"(a) : "l"(p));
    return a;
}
__device__ __forceinline__ void cp16(uint32_t dst, const void* src) {
    asm volatile("cp.async.cg.shared.global [%0], [%1], 16;" :: "r"(dst), "l"(src) : "memory");
}
#define CP_COMMIT() asm volatile("cp.async.commit_group;" ::: "memory")
#define CP_WAIT1()  asm volatile("cp.async.wait_group 1;" ::: "memory")

__device__ __forceinline__ void ldsm4(uint32_t addr, uint32_t& r0, uint32_t& r1, uint32_t& r2, uint32_t& r3) {
    asm volatile("ldmatrix.sync.aligned.m8n8.x4.shared.b16 {%0,%1,%2,%3}, [%4];"
                 : "=r"(r0), "=r"(r1), "=r"(r2), "=r"(r3) : "r"(addr));
}
// NON-volatile: pure register op -> ptxas may interleave MMAs with LDSMs.
__device__ __forceinline__ void mma16816(float* c, const uint32_t* a, const uint32_t* b) {
    asm("mma.sync.aligned.m16n8k16.row.col.f32.bf16.bf16.f32 "
        "{%0,%1,%2,%3}, {%4,%5,%6,%7}, {%8,%9}, {%0,%1,%2,%3};"
        : "+f"(c[0]), "+f"(c[1]), "+f"(c[2]), "+f"(c[3])
        : "r"(a[0]), "r"(a[1]), "r"(a[2]), "r"(a[3]), "r"(b[0]), "r"(b[1]));
}
__device__ __forceinline__ void split2(float v, __nv_bfloat16& hi, __nv_bfloat16& lo) {
    hi = __float2bfloat16(v);
    lo = __float2bfloat16(v - __bfloat162float(hi));
}
__device__ __forceinline__ float sigmoidf_(float x) { return 1.0f / (1.0f + __expf(-x)); }

// swizzled byte offset within an Nx64B tile: row r, 16B chunk c (0..3)
__device__ __forceinline__ uint32_t swz(int r, int c) {
    return (uint32_t)(r * 64 + ((c ^ ((r >> 1) & 3)) << 4));
}

// ---------------- split-precision HMMA GEMM (+ fused LSTM cell) ----------------
// A operand per chunk: chunk < xchunks -> Ax (ldax), else Ah (HDIM ld, k rebased).
// mode 0 (gates): gate-permuted output; epilogue applies LSTM cell, updates cstate,
//                 split-writes h into hw_hi/lo [MROWS x HDIM]
// mode 1 (cls):   writes Co (ld DSTEPS*FDIM); split-writes result to ox_hi/lo [MROWS x FDIM]
__global__ void __launch_bounds__(NTHR, 2)
gemm_hmma(const __nv_bfloat16* __restrict__ Axh, const __nv_bfloat16* __restrict__ Axl, int ldax,
          const __nv_bfloat16* __restrict__ Ahh, const __nv_bfloat16* __restrict__ Ahl, int xchunks,
          const __nv_bfloat16* __restrict__ Whi, const __nv_bfloat16* __restrict__ Wlo, int ldw,
          int K,
          const float* __restrict__ bias,
          float* __restrict__ cstate,
          float* __restrict__ Co,
          __nv_bfloat16* __restrict__ ox_hi, __nv_bfloat16* __restrict__ ox_lo,
          __nv_bfloat16* __restrict__ hw_hi, __nv_bfloat16* __restrict__ hw_lo,
          int mode, int first)
{
    extern __shared__ char smem[];
    const uint32_t sb = smem_u32(smem);
    const int tid = threadIdx.x;
    const int lane = tid & 31;
    const int wid = tid >> 5;
    const int wm = wid & 1;        // 0..1 -> 64-row slice
    const int wn = wid >> 1;       // 0..3 -> 32-col slice
    const int bm = blockIdx.y, bn = blockIdx.x;
    const int nch = K / BK;

    const char* srcX0 = (const char*)Axh + (size_t)(bm * BM) * ldax * 2;
    const char* srcX1 = (const char*)Axl + (size_t)(bm * BM) * ldax * 2;
    const char* srcH0 = Ahh ? (const char*)Ahh + (size_t)(bm * BM) * HDIM * 2 : nullptr;
    const char* srcH1 = Ahl ? (const char*)Ahl + (size_t)(bm * BM) * HDIM * 2 : nullptr;
    const char* srcW0 = (const char*)Whi + (size_t)(bn * BN) * ldw * 2;
    const char* srcW1 = (const char*)Wlo + (size_t)(bn * BN) * ldw * 2;
    const size_t ldxb = (size_t)ldax * 2;
    const size_t ldhb = (size_t)HDIM * 2;
    const size_t ldwb = (size_t)ldw * 2;

    auto load_stage = [&](int slot, int chunk) {
        const uint32_t stg = sb + slot * STAGE_B;
        const bool useH = (chunk >= xchunks);
        const char* a0 = useH ? srcH0 : srcX0;
        const char* a1 = useH ? srcH1 : srcX1;
        const size_t ldab = useH ? ldhb : ldxb;
        const int kba = (useH ? (chunk - xchunks) : chunk) * (BK * 2);
        const int kbw = chunk * (BK * 2);
#pragma unroll
        for (int it = 0; it < GRANULES / NTHR; it++) {
            const int g = tid + it * NTHR;
            const char* src; uint32_t dst; int idx; size_t ldb; int kb;
            if (g < 512)       { idx = g;        src = a0;    dst = stg;                            ldb = ldab; kb = kba; }
            else if (g < 1024) { idx = g - 512;  src = a1;    dst = stg + A_TILE_B;                 ldb = ldab; kb = kba; }
            else if (g < 1536) { idx = g - 1024; src = srcW0; dst = stg + 2 * A_TILE_B;             ldb = ldwb; kb = kbw; }
            else               { idx = g - 1536; src = srcW1; dst = stg + 2 * A_TILE_B + W_TILE_B;  ldb = ldwb; kb = kbw; }
            const int r = idx >> 2, c = idx & 3;
            cp16(dst + swz(r, c), src + (size_t)r * ldb + kb + c * 16);
        }
    };

    float acc[4][4][4];
#pragma unroll
    for (int mt = 0; mt < 4; mt++)
#pragma unroll
        for (int nt = 0; nt < 4; nt++)
#pragma unroll
            for (int e = 0; e < 4; e++) acc[mt][nt][e] = 0.0f;

    load_stage(0, 0); CP_COMMIT();
    load_stage(1, 1); CP_COMMIT();

    const int lrow = lane & 15;
    const int lchk = lane >> 4;

    // loop-invariant swizzled offsets (per kh half): A rows and W rows
    uint32_t offA[2][4], offW[2][2];
#pragma unroll
    for (int kh = 0; kh < 2; kh++) {
        const int cc = kh * 2 + lchk;
#pragma unroll
        for (int mt = 0; mt < 4; mt++)
            offA[kh][mt] = swz(wm * 64 + mt * 16 + lrow, cc);
#pragma unroll
        for (int np = 0; np < 2; np++)
            offW[kh][np] = swz(wn * 32 + np * 16 + lrow, cc);
    }

    for (int i = 0; i < nch; i++) {
        CP_WAIT1();
        __syncthreads();
        if (i + 2 < nch) load_stage((i + 2) % STAGES, i + 2);
        CP_COMMIT();

        const uint32_t stg = sb + (i % STAGES) * STAGE_B;
        const uint32_t sA_hi = stg;
        const uint32_t sA_lo = stg + A_TILE_B;
        const uint32_t sW_hi = stg + 2 * A_TILE_B;
        const uint32_t sW_lo = stg + 2 * A_TILE_B + W_TILE_B;

#pragma unroll
        for (int kh = 0; kh < 2; kh++) {
            uint32_t ah[4][4], bh[4][2];
#pragma unroll
            for (int mt = 0; mt < 4; mt++)
                ldsm4(sA_hi + offA[kh][mt], ah[mt][0], ah[mt][1], ah[mt][2], ah[mt][3]);
#pragma unroll
            for (int np = 0; np < 2; np++) {
                uint32_t r0, r1, r2, r3;
                ldsm4(sW_hi + offW[kh][np], r0, r1, r2, r3);
                bh[np * 2][0] = r0; bh[np * 2 + 1][0] = r1;
                bh[np * 2][1] = r2; bh[np * 2 + 1][1] = r3;
            }
#pragma unroll
            for (int mt = 0; mt < 4; mt++)
#pragma unroll
                for (int nt = 0; nt < 4; nt++)
                    mma16816(acc[mt][nt], ah[mt], bh[nt]);        // hi*hi
            {
                uint32_t al[4][4];
#pragma unroll
                for (int mt = 0; mt < 4; mt++)
                    ldsm4(sA_lo + offA[kh][mt], al[mt][0], al[mt][1], al[mt][2], al[mt][3]);
#pragma unroll
                for (int mt = 0; mt < 4; mt++)
#pragma unroll
                    for (int nt = 0; nt < 4; nt++)
                        mma16816(acc[mt][nt], al[mt], bh[nt]);    // lo*hi
            }
            {
                uint32_t bl[4][2];
#pragma unroll
                for (int np = 0; np < 2; np++) {
                    uint32_t r0, r1, r2, r3;
                    ldsm4(sW_lo + offW[kh][np], r0, r1, r2, r3);
                    bl[np * 2][0] = r0; bl[np * 2 + 1][0] = r1;
                    bl[np * 2][1] = r2; bl[np * 2 + 1][1] = r3;
                }
#pragma unroll
                for (int mt = 0; mt < 4; mt++)
#pragma unroll
                    for (int nt = 0; nt < 4; nt++)
                        mma16816(acc[mt][nt], ah[mt], bl[nt]);    // hi*lo
            }
        }
        __syncthreads();
    }

    // ---------------- epilogue ----------------
    const int rbase = bm * BM + wm * 64;
    const int cbase = bn * BN + wn * 32;
    const int qr = lane >> 2;            // 0..7
    const int qc = (lane & 3) * 2;       // 0,2,4,6

    if (mode == 0) {
        // gate-permuted columns: p = j*4 + gate (i,f,g,o). Even lane holds (p,p+1)=(i,f),
        // odd partner holds (p+2,p+3)=(g,o); shfl_xor(1) assembles the quad.
#pragma unroll
        for (int mt = 0; mt < 4; mt++) {
#pragma unroll
            for (int nt = 0; nt < 4; nt++) {
                const int p = cbase + nt * 8 + qc;
                const float bv0 = bias[p], bv1 = bias[p + 1];
                const float v0 = acc[mt][nt][0] + bv0;
                const float v1 = acc[mt][nt][1] + bv1;
                const float v2 = acc[mt][nt][2] + bv0;
                const float v3 = acc[mt][nt][3] + bv1;
                const float x0 = __shfl_xor_sync(0xffffffffu, v0, 1);
                const float x1 = __shfl_xor_sync(0xffffffffu, v1, 1);
                const float x2 = __shfl_xor_sync(0xffffffffu, v2, 1);
                const float x3 = __shfl_xor_sync(0xffffffffu, v3, 1);
                if (!(lane & 1)) {
                    const int j = p >> 2;            // hidden unit
                    const int r0 = rbase + mt * 16 + qr;
#pragma unroll
                    for (int half = 0; half < 2; half++) {
                        const int row = r0 + half * 8;
                        const float iv = half ? v2 : v0;
                        const float fv = half ? v3 : v1;
                        const float gv = half ? x2 : x0;
                        const float ov = half ? x3 : x1;
                        const float cold = first ? 0.0f : cstate[(size_t)row * HDIM + j];
                        const float cn = sigmoidf_(fv) * cold + sigmoidf_(iv) * tanhf(gv);
                        cstate[(size_t)row * HDIM + j] = cn;
                        const float h = sigmoidf_(ov) * tanhf(cn);
                        __nv_bfloat16 hh, hl; split2(h, hh, hl);
                        hw_hi[(size_t)row * HDIM + j] = hh;
                        hw_lo[(size_t)row * HDIM + j] = hl;
                    }
                }
            }
        }
    } else {
#pragma unroll
        for (int mt = 0; mt < 4; mt++) {
#pragma unroll
            for (int nt = 0; nt < 4; nt++) {
                const int col = cbase + nt * 8 + qc;
                const float bv0 = bias[col], bv1 = bias[col + 1];
#pragma unroll
                for (int half = 0; half < 2; half++) {
                    const int row = rbase + mt * 16 + qr + half * 8;
                    const float v0 = acc[mt][nt][half * 2 + 0] + bv0;
                    const float v1 = acc[mt][nt][half * 2 + 1] + bv1;
                    *(float2*)(Co + (size_t)row * (DSTEPS * FDIM) + col) = make_float2(v0, v1);
                    __nv_bfloat16 h0, l0, h1, l1;
                    split2(v0, h0, l0);
                    split2(v1, h1, l1);
                    *(__nv_bfloat162*)(ox_hi + (size_t)row * FDIM + col) = __nv_bfloat162(h0, h1);
                    *(__nv_bfloat162*)(ox_lo + (size_t)row * FDIM + col) = __nv_bfloat162(l0, l1);
                }
            }
        }
    }
}

// ---------------- elementwise prep kernels ----------------
__global__ void split_act(const float* __restrict__ x,
                          __nv_bfloat16* __restrict__ oh, __nv_bfloat16* __restrict__ ol)
{
    const int idx = blockIdx.x * blockDim.x + threadIdx.x;   // MROWS*FDIM
    const float v = x[idx];
    __nv_bfloat16 hi, lo; split2(v, hi, lo);
    oh[idx] = hi; ol[idx] = lo;
}

// gates weights gate-permuted: output row p = j*4 + gate, src row = gate*H + j
__global__ void split_weights(const float* __restrict__ W_ih, const float* __restrict__ W_hh,
                              const float* __restrict__ W_cls,
                              const float* __restrict__ b_ih, const float* __restrict__ b_hh,
                              __nv_bfloat16* __restrict__ wgh, __nv_bfloat16* __restrict__ wgl,
                              __nv_bfloat16* __restrict__ wch, __nv_bfloat16* __restrict__ wcl,
                              float* __restrict__ biasg)
{
    const int idx = blockIdx.x * blockDim.x + threadIdx.x;
    const int NG = GDIM * KFUSE;
    if (idx < NG) {
        const int p = idx / KFUSE, col = idx - p * KFUSE;
        const int src_n = (p & 3) * HDIM + (p >> 2);
        float v = (col < FDIM) ? W_ih[(size_t)src_n * FDIM + col]
                               : W_hh[(size_t)src_n * HDIM + (col - FDIM)];
        __nv_bfloat16 hi, lo; split2(v, hi, lo);
        wgh[idx] = hi; wgl[idx] = lo;
        if (idx < GDIM) {
            const int sn = (idx & 3) * HDIM + (idx >> 2);
            biasg[idx] = b_ih[sn] + b_hh[sn];
        }
    } else {
        const int i2 = idx - NG;                // FDIM*HDIM
        float v = W_cls[i2];
        __nv_bfloat16 hi, lo; split2(v, hi, lo);
        wch[i2] = hi; wcl[i2] = lo;
    }
}

// ---------------- launch ----------------
extern "C" void kernel_launch(void* const* d_in, const int* in_sizes, int n_in,
                              void* d_out, int out_size)
{
    const float* x     = (const float*)d_in[0];
    const float* W_ih  = (const float*)d_in[1];
    const float* W_hh  = (const float*)d_in[2];
    const float* b_ih  = (const float*)d_in[3];
    const float* b_hh  = (const float*)d_in[4];
    const float* W_cls = (const float*)d_in[5];
    const float* b_cls = (const float*)d_in[6];
    float* out = (float*)d_out;                    // [8192 rows, 8 steps, 1024]

    __nv_bfloat16 *p_oh, *p_ol, *p_wgh, *p_wgl, *p_wch, *p_wcl;
    __nv_bfloat16 *p_hh[2], *p_hl[2];
    float *p_biasg, *p_c;
    cudaGetSymbolAddress((void**)&p_oh,  g_out_hi);
    cudaGetSymbolAddress((void**)&p_ol,  g_out_lo);
    {
        __nv_bfloat16* base;
        cudaGetSymbolAddress((void**)&base, g_h_hi);
        p_hh[0] = base; p_hh[1] = base + (size_t)MROWS * HDIM;
        cudaGetSymbolAddress((void**)&base, g_h_lo);
        p_hl[0] = base; p_hl[1] = base + (size_t)MROWS * HDIM;
    }
    cudaGetSymbolAddress((void**)&p_wgh, g_wg_hi);
    cudaGetSymbolAddress((void**)&p_wgl, g_wg_lo);
    cudaGetSymbolAddress((void**)&p_wch, g_wc_hi);
    cudaGetSymbolAddress((void**)&p_wcl, g_wc_lo);
    cudaGetSymbolAddress((void**)&p_biasg, g_biasg);
    cudaGetSymbolAddress((void**)&p_c,   g_c);

    cudaFuncSetAttribute(gemm_hmma, cudaFuncAttributeMaxDynamicSharedMemorySize, SMEM_TOTAL);

    split_act<<<(MROWS * FDIM) / 256, 256>>>(x, p_oh, p_ol);
    split_weights<<<(GDIM * KFUSE + FDIM * HDIM) / 256, 256>>>(W_ih, W_hh, W_cls, b_ih, b_hh,
                                                               p_wgh, p_wgl, p_wch, p_wcl, p_biasg);

    const dim3 gridG(GDIM / BN, MROWS / BM);   // (16, 64)
    const dim3 gridC(FDIM / BN, MROWS / BM);   // (8, 64)

    for (int d = 0; d < DSTEPS; d++) {
        const int wb = d & 1;                 // h write buffer
        const int rb = (d + 1) & 1;           // h read buffer (prev step)
        // gates GEMM + fused LSTM cell. Step 0: K=1024 (h0 == 0, skip h chunks).
        const int Kg = (d == 0) ? FDIM : KFUSE;
        gemm_hmma<<<gridG, NTHR, SMEM_TOTAL>>>(p_oh, p_ol, FDIM,
                                               p_hh[rb], p_hl[rb], FDIM / BK,
                                               p_wgh, p_wgl, KFUSE,
                                               Kg, p_biasg,
                                               p_c, nullptr,
                                               nullptr, nullptr,
                                               p_hh[wb], p_hl[wb],
                                               0, d == 0 ? 1 : 0);
        // out = h @ W_cls^T + b_cls -> d_out slice d; split-write into out buffers
        gemm_hmma<<<gridC, NTHR, SMEM_TOTAL>>>(p_hh[wb], p_hl[wb], HDIM,
                                               nullptr, nullptr, 1 << 30,
                                               p_wch, p_wcl, HDIM,
                                               HDIM, b_cls,
                                               nullptr, out + (size_t)d * FDIM,
                                               p_oh, p_ol,
                                               nullptr, nullptr,
                                               1, 0);
    }
}

// round 8
// speedup vs baseline: 1.3493x; 1.3493x over previous
#include <cuda_runtime.h>
#include <cuda_fp16.h>
#include <cstdint>
#include <cstddef>

// ---------------- problem constants ----------------
#define MROWS 8192
#define FDIM  1024
#define HDIM  512
#define GDIM  2048
#define KFUSE 1536
#define DSTEPS 8

// ---------------- GEMM tile config ----------------
#define BM 128
#define BN 128
#define BK 32                 // fp16 elems per chunk (64 bytes per row)
#define STAGES 3
#define NTHR 256
#define TILE_B (128*64)       // 8192 bytes per 128x32 fp16 tile
#define STAGE_B (3*TILE_B)    // Ahi, Alo, W = 24576
#define SMEM_TOTAL (STAGES*STAGE_B)   // 73728

// ---------------- scratch (device globals) ----------------
__device__ __align__(256) __half g_out_hi[(size_t)MROWS*FDIM];   // x-part of A (cls output)
__device__ __align__(256) __half g_out_lo[(size_t)MROWS*FDIM];
__device__ __align__(256) __half g_h_hi[2][(size_t)MROWS*HDIM];  // double-buffered h
__device__ __align__(256) __half g_h_lo[2][(size_t)MROWS*HDIM];
__device__ __align__(256) __half g_wg[(size_t)GDIM*KFUSE];       // gate-permuted fused W (fp16)
__device__ __align__(256) __half g_wc[(size_t)FDIM*HDIM];        // W_cls (fp16)
__device__ __align__(256) float g_biasg[GDIM];                   // permuted b_ih+b_hh
__device__ __align__(256) float g_c[(size_t)MROWS*HDIM];

// ---------------- helpers ----------------
__device__ __forceinline__ uint32_t smem_u32(const void* p) {
    uint32_t a;
    asm("{ .reg .u64 t; cvta.to.shared.u64 t, %1; cvt.u32.u64 %0, t; }" : "=r"(a) : "l"(p));
    return a;
}
__device__ __forceinline__ void cp16(uint32_t dst, const void* src) {
    asm volatile("cp.async.cg.shared.global [%0], [%1], 16;" :: "r"(dst), "l"(src) : "memory");
}
#define CP_COMMIT() asm volatile("cp.async.commit_group;" ::: "memory")
#define CP_WAIT1()  asm volatile("cp.async.wait_group 1;" ::: "memory")

__device__ __forceinline__ void ldsm4(uint32_t addr, uint32_t& r0, uint32_t& r1, uint32_t& r2, uint32_t& r3) {
    asm volatile("ldmatrix.sync.aligned.m8n8.x4.shared.b16 {%0,%1,%2,%3}, [%4];"
                 : "=r"(r0), "=r"(r1), "=r"(r2), "=r"(r3) : "r"(addr));
}
__device__ __forceinline__ void mma16816(float* c, const uint32_t* a, const uint32_t* b) {
    asm("mma.sync.aligned.m16n8k16.row.col.f32.f16.f16.f32 "
        "{%0,%1,%2,%3}, {%4,%5,%6,%7}, {%8,%9}, {%0,%1,%2,%3};"
        : "+f"(c[0]), "+f"(c[1]), "+f"(c[2]), "+f"(c[3])
        : "r"(a[0]), "r"(a[1]), "r"(a[2]), "r"(a[3]), "r"(b[0]), "r"(b[1]));
}
__device__ __forceinline__ void split2h(float v, __half& hi, __half& lo) {
    hi = __float2half(v);
    lo = __float2half(v - __half2float(hi));
}
__device__ __forceinline__ float sigmoidf_(float x) { return 1.0f / (1.0f + __expf(-x)); }

// swizzled byte offset within an Nx64B tile: row r, 16B chunk c (0..3)
__device__ __forceinline__ uint32_t swz(int r, int c) {
    return (uint32_t)(r * 64 + ((c ^ ((r >> 1) & 3)) << 4));
}

// ---------------- split-precision fp16 HMMA GEMM (+ fused LSTM cell) ----------------
// D = (Ahi + Alo) @ W^T + bias  — 2 fp16 MMA passes; W quantized once to fp16.
// A operand per chunk: chunk < xchunks -> x buffers (ldax), else h buffers (HDIM ld).
// mode 0 (gates): gate-permuted output; epilogue applies LSTM cell, updates cstate,
//                 split-writes h into hw_hi/lo [MROWS x HDIM]
// mode 1 (cls):   writes Co (ld DSTEPS*FDIM); split-writes result to ox_hi/lo [MROWS x FDIM]
__global__ void __launch_bounds__(NTHR, 2)
gemm_hmma(const __half* __restrict__ Axh, const __half* __restrict__ Axl, int ldax,
          const __half* __restrict__ Ahh, const __half* __restrict__ Ahl, int xchunks,
          const __half* __restrict__ W, int ldw,
          int K,
          const float* __restrict__ bias,
          float* __restrict__ cstate,
          float* __restrict__ Co,
          __half* __restrict__ ox_hi, __half* __restrict__ ox_lo,
          __half* __restrict__ hw_hi, __half* __restrict__ hw_lo,
          int mode, int first)
{
    extern __shared__ char smem[];
    const uint32_t sb = smem_u32(smem);
    const int tid = threadIdx.x;
    const int lane = tid & 31;
    const int wid = tid >> 5;
    const int wm = wid & 1;        // 0..1 -> 64-row slice
    const int wn = wid >> 1;       // 0..3 -> 32-col slice
    const int bm = blockIdx.y, bn = blockIdx.x;
    const int nch = K / BK;

    // ---- loader precompute: each thread owns granule idx (tid) and (tid+256) in
    // each of the 3 tiles. dst swizzle for idx+256 is dOff+4096 (XOR bits unchanged).
    const int r0g = tid >> 2, c0g = tid & 3;          // granule row/chunk for idx=tid
    const uint32_t dOff = swz(r0g, c0g);              // + tile base; +4096 for 2nd half
    const size_t ldxb = (size_t)ldax * 2;
    const size_t ldhb = (size_t)HDIM * 2;
    const size_t ldwb = (size_t)ldw * 2;
    // per-thread source bases (row*ld + c*16 folded in)
    const char* pXh = (const char*)Axh + (size_t)(bm * BM + r0g) * ldxb + c0g * 16;
    const char* pXl = (const char*)Axl + (size_t)(bm * BM + r0g) * ldxb + c0g * 16;
    const char* pHh = Ahh ? (const char*)Ahh + (size_t)(bm * BM + r0g) * ldhb + c0g * 16 : nullptr;
    const char* pHl = Ahl ? (const char*)Ahl + (size_t)(bm * BM + r0g) * ldhb + c0g * 16 : nullptr;
    const char* pW  = (const char*)W + (size_t)(bn * BN + r0g) * ldwb + c0g * 16;
    const size_t ldx64 = ldxb * 64, ldh64 = ldhb * 64, ldw64 = ldwb * 64;

    auto load_stage = [&](int slot, int chunk) {
        const uint32_t stg = sb + slot * STAGE_B;
        const bool useH = (chunk >= xchunks);
        const char* a0 = useH ? pHh : pXh;
        const char* a1 = useH ? pHl : pXl;
        const size_t lda64 = useH ? ldh64 : ldx64;
        const size_t kba = (size_t)(useH ? (chunk - xchunks) : chunk) * 64;
        const size_t kbw = (size_t)chunk * 64;
        cp16(stg + dOff,                       a0 + kba);
        cp16(stg + dOff + 4096,                a0 + kba + lda64);
        cp16(stg + TILE_B + dOff,              a1 + kba);
        cp16(stg + TILE_B + dOff + 4096,       a1 + kba + lda64);
        cp16(stg + 2 * TILE_B + dOff,          pW + kbw);
        cp16(stg + 2 * TILE_B + dOff + 4096,   pW + kbw + ldw64);
    };

    float acc[4][4][4];
#pragma unroll
    for (int mt = 0; mt < 4; mt++)
#pragma unroll
        for (int nt = 0; nt < 4; nt++)
#pragma unroll
            for (int e = 0; e < 4; e++) acc[mt][nt][e] = 0.0f;

    load_stage(0, 0); CP_COMMIT();
    load_stage(1, 1); CP_COMMIT();

    const int lrow = lane & 15;
    const int lchk = lane >> 4;

    // loop-invariant swizzled ldmatrix offsets per kh half
    uint32_t offA[2][4], offW[2][2];
#pragma unroll
    for (int kh = 0; kh < 2; kh++) {
        const int cc = kh * 2 + lchk;
#pragma unroll
        for (int mt = 0; mt < 4; mt++)
            offA[kh][mt] = swz(wm * 64 + mt * 16 + lrow, cc);
#pragma unroll
        for (int np = 0; np < 2; np++)
            offW[kh][np] = swz(wn * 32 + np * 16 + lrow, cc);
    }

    for (int i = 0; i < nch; i++) {
        CP_WAIT1();
        __syncthreads();
        if (i + 2 < nch) load_stage((i + 2) % STAGES, i + 2);
        CP_COMMIT();

        const uint32_t stg = sb + (i % STAGES) * STAGE_B;
        const uint32_t sA_hi = stg;
        const uint32_t sA_lo = stg + TILE_B;
        const uint32_t sW = stg + 2 * TILE_B;

#pragma unroll
        for (int kh = 0; kh < 2; kh++) {
            uint32_t b[4][2];
#pragma unroll
            for (int np = 0; np < 2; np++) {
                uint32_t r0, r1, r2, r3;
                ldsm4(sW + offW[kh][np], r0, r1, r2, r3);
                b[np * 2][0] = r0; b[np * 2 + 1][0] = r1;
                b[np * 2][1] = r2; b[np * 2 + 1][1] = r3;
            }
            {
                uint32_t ah[4][4];
#pragma unroll
                for (int mt = 0; mt < 4; mt++)
                    ldsm4(sA_hi + offA[kh][mt], ah[mt][0], ah[mt][1], ah[mt][2], ah[mt][3]);
#pragma unroll
                for (int mt = 0; mt < 4; mt++)
#pragma unroll
                    for (int nt = 0; nt < 4; nt++)
                        mma16816(acc[mt][nt], ah[mt], b[nt]);     // hi pass
            }
            {
                uint32_t al[4][4];
#pragma unroll
                for (int mt = 0; mt < 4; mt++)
                    ldsm4(sA_lo + offA[kh][mt], al[mt][0], al[mt][1], al[mt][2], al[mt][3]);
#pragma unroll
                for (int mt = 0; mt < 4; mt++)
#pragma unroll
                    for (int nt = 0; nt < 4; nt++)
                        mma16816(acc[mt][nt], al[mt], b[nt]);     // lo pass
            }
        }
        __syncthreads();
    }

    // ---------------- epilogue ----------------
    const int rbase = bm * BM + wm * 64;
    const int cbase = bn * BN + wn * 32;
    const int qr = lane >> 2;            // 0..7
    const int qc = (lane & 3) * 2;       // 0,2,4,6

    if (mode == 0) {
        // gate-permuted columns: p = j*4 + gate (i,f,g,o). Even lane holds (p,p+1)=(i,f),
        // odd partner holds (p+2,p+3)=(g,o); shfl_xor(1) assembles the quad.
#pragma unroll
        for (int mt = 0; mt < 4; mt++) {
#pragma unroll
            for (int nt = 0; nt < 4; nt++) {
                const int p = cbase + nt * 8 + qc;
                const float bv0 = bias[p], bv1 = bias[p + 1];
                const float v0 = acc[mt][nt][0] + bv0;
                const float v1 = acc[mt][nt][1] + bv1;
                const float v2 = acc[mt][nt][2] + bv0;
                const float v3 = acc[mt][nt][3] + bv1;
                const float x0 = __shfl_xor_sync(0xffffffffu, v0, 1);
                const float x1 = __shfl_xor_sync(0xffffffffu, v1, 1);
                const float x2 = __shfl_xor_sync(0xffffffffu, v2, 1);
                const float x3 = __shfl_xor_sync(0xffffffffu, v3, 1);
                if (!(lane & 1)) {
                    const int j = p >> 2;            // hidden unit
                    const int r0 = rbase + mt * 16 + qr;
#pragma unroll
                    for (int half = 0; half < 2; half++) {
                        const int row = r0 + half * 8;
                        const float iv = half ? v2 : v0;
                        const float fv = half ? v3 : v1;
                        const float gv = half ? x2 : x0;
                        const float ov = half ? x3 : x1;
                        const float cold = first ? 0.0f : cstate[(size_t)row * HDIM + j];
                        const float cn = sigmoidf_(fv) * cold + sigmoidf_(iv) * tanhf(gv);
                        cstate[(size_t)row * HDIM + j] = cn;
                        const float h = sigmoidf_(ov) * tanhf(cn);
                        __half hh, hl; split2h(h, hh, hl);
                        hw_hi[(size_t)row * HDIM + j] = hh;
                        hw_lo[(size_t)row * HDIM + j] = hl;
                    }
                }
            }
        }
    } else {
#pragma unroll
        for (int mt = 0; mt < 4; mt++) {
#pragma unroll
            for (int nt = 0; nt < 4; nt++) {
                const int col = cbase + nt * 8 + qc;
                const float bv0 = bias[col], bv1 = bias[col + 1];
#pragma unroll
                for (int half = 0; half < 2; half++) {
                    const int row = rbase + mt * 16 + qr + half * 8;
                    const float v0 = acc[mt][nt][half * 2 + 0] + bv0;
                    const float v1 = acc[mt][nt][half * 2 + 1] + bv1;
                    *(float2*)(Co + (size_t)row * (DSTEPS * FDIM) + col) = make_float2(v0, v1);
                    __half h0, l0, h1, l1;
                    split2h(v0, h0, l0);
                    split2h(v1, h1, l1);
                    *(__half2*)(ox_hi + (size_t)row * FDIM + col) = __halves2half2(h0, h1);
                    *(__half2*)(ox_lo + (size_t)row * FDIM + col) = __halves2half2(l0, l1);
                }
            }
        }
    }
}

// ---------------- elementwise prep kernels ----------------
__global__ void split_act(const float* __restrict__ x,
                          __half* __restrict__ oh, __half* __restrict__ ol)
{
    const int idx = blockIdx.x * blockDim.x + threadIdx.x;   // MROWS*FDIM
    const float v = x[idx];
    __half hi, lo; split2h(v, hi, lo);
    oh[idx] = hi; ol[idx] = lo;
}

// gates weights gate-permuted fp16: output row p = j*4 + gate, src row = gate*H + j
__global__ void split_weights(const float* __restrict__ W_ih, const float* __restrict__ W_hh,
                              const float* __restrict__ W_cls,
                              const float* __restrict__ b_ih, const float* __restrict__ b_hh,
                              __half* __restrict__ wg, __half* __restrict__ wc,
                              float* __restrict__ biasg)
{
    const int idx = blockIdx.x * blockDim.x + threadIdx.x;
    const int NG = GDIM * KFUSE;
    if (idx < NG) {
        const int p = idx / KFUSE, col = idx - p * KFUSE;
        const int src_n = (p & 3) * HDIM + (p >> 2);
        const float v = (col < FDIM) ? W_ih[(size_t)src_n * FDIM + col]
                                     : W_hh[(size_t)src_n * HDIM + (col - FDIM)];
        wg[idx] = __float2half(v);
        if (idx < GDIM) {
            const int sn = (idx & 3) * HDIM + (idx >> 2);
            biasg[idx] = b_ih[sn] + b_hh[sn];
        }
    } else {
        const int i2 = idx - NG;                // FDIM*HDIM
        wc[i2] = __float2half(W_cls[i2]);
    }
}

// ---------------- launch ----------------
extern "C" void kernel_launch(void* const* d_in, const int* in_sizes, int n_in,
                              void* d_out, int out_size)
{
    const float* x     = (const float*)d_in[0];
    const float* W_ih  = (const float*)d_in[1];
    const float* W_hh  = (const float*)d_in[2];
    const float* b_ih  = (const float*)d_in[3];
    const float* b_hh  = (const float*)d_in[4];
    const float* W_cls = (const float*)d_in[5];
    const float* b_cls = (const float*)d_in[6];
    float* out = (float*)d_out;                    // [8192 rows, 8 steps, 1024]

    __half *p_oh, *p_ol, *p_wg, *p_wc;
    __half *p_hh[2], *p_hl[2];
    float *p_biasg, *p_c;
    cudaGetSymbolAddress((void**)&p_oh, g_out_hi);
    cudaGetSymbolAddress((void**)&p_ol, g_out_lo);
    {
        __half* base;
        cudaGetSymbolAddress((void**)&base, g_h_hi);
        p_hh[0] = base; p_hh[1] = base + (size_t)MROWS * HDIM;
        cudaGetSymbolAddress((void**)&base, g_h_lo);
        p_hl[0] = base; p_hl[1] = base + (size_t)MROWS * HDIM;
    }
    cudaGetSymbolAddress((void**)&p_wg, g_wg);
    cudaGetSymbolAddress((void**)&p_wc, g_wc);
    cudaGetSymbolAddress((void**)&p_biasg, g_biasg);
    cudaGetSymbolAddress((void**)&p_c, g_c);

    cudaFuncSetAttribute(gemm_hmma, cudaFuncAttributeMaxDynamicSharedMemorySize, SMEM_TOTAL);

    split_act<<<(MROWS * FDIM) / 256, 256>>>(x, p_oh, p_ol);
    split_weights<<<(GDIM * KFUSE + FDIM * HDIM) / 256, 256>>>(W_ih, W_hh, W_cls, b_ih, b_hh,
                                                               p_wg, p_wc, p_biasg);

    const dim3 gridG(GDIM / BN, MROWS / BM);   // (16, 64)
    const dim3 gridC(FDIM / BN, MROWS / BM);   // (8, 64)

    for (int d = 0; d < DSTEPS; d++) {
        const int wb = d & 1;                 // h write buffer
        const int rb = (d + 1) & 1;           // h read buffer (prev step)
        // gates GEMM + fused LSTM cell. Step 0: K=1024 (h0 == 0, skip h chunks).
        const int Kg = (d == 0) ? FDIM : KFUSE;
        gemm_hmma<<<gridG, NTHR, SMEM_TOTAL>>>(p_oh, p_ol, FDIM,
                                               p_hh[rb], p_hl[rb], FDIM / BK,
                                               p_wg, KFUSE,
                                               Kg, p_biasg,
                                               p_c, nullptr,
                                               nullptr, nullptr,
                                               p_hh[wb], p_hl[wb],
                                               0, d == 0 ? 1 : 0);
        // out = h @ W_cls^T + b_cls -> d_out slice d; split-write into out buffers
        gemm_hmma<<<gridC, NTHR, SMEM_TOTAL>>>(p_hh[wb], p_hl[wb], HDIM,
                                               nullptr, nullptr, 1 << 30,
                                               p_wc, HDIM,
                                               HDIM, b_cls,
                                               nullptr, out + (size_t)d * FDIM,
                                               p_oh, p_ol,
                                               nullptr, nullptr,
                                               1, 0);
    }
}

// round 9
// speedup vs baseline: 2.2822x; 1.6914x over previous
#include <cuda_runtime.h>
#include <cuda_fp16.h>
#include <cstdint>
#include <cstddef>

// ---------------- problem constants ----------------
#define MROWS 8192
#define FDIM  1024
#define HDIM  512
#define GDIM  2048
#define KFUSE 1536
#define DSTEPS 8

// ---------------- GEMM tile config ----------------
#define BM 128
#define BN 128
#define BK 32                 // fp16 elems per chunk (64 bytes per row)
#define STAGES 4
#define NTHR 256
#define TILE_B (128*64)       // 8192 bytes per 128x32 fp16 tile
#define STAGE_B (2*TILE_B)    // A, W = 16384
#define SMEM_TOTAL (STAGES*STAGE_B)   // 65536

// ---------------- scratch (device globals) ----------------
__device__ __align__(256) __half g_out[(size_t)MROWS*FDIM];     // x-part of A (cls output)
__device__ __align__(256) __half g_h[2][(size_t)MROWS*HDIM];    // double-buffered h
__device__ __align__(256) __half g_wg[(size_t)GDIM*KFUSE];      // gate-permuted fused W (fp16)
__device__ __align__(256) __half g_wc[(size_t)FDIM*HDIM];       // W_cls (fp16)
__device__ __align__(256) float g_biasg[GDIM];                  // permuted b_ih+b_hh
__device__ __align__(256) float g_c[(size_t)MROWS*HDIM];

// ---------------- helpers ----------------
__device__ __forceinline__ uint32_t smem_u32(const void* p) {
    uint32_t a;
    asm("{ .reg .u64 t; cvta.to.shared.u64 t, %1; cvt.u32.u64 %0, t; }" : "=r"(a) : "l"(p));
    return a;
}
__device__ __forceinline__ void cp16(uint32_t dst, const void* src) {
    asm volatile("cp.async.cg.shared.global [%0], [%1], 16;" :: "r"(dst), "l"(src) : "memory");
}
#define CP_COMMIT() asm volatile("cp.async.commit_group;" ::: "memory")
#define CP_WAIT2()  asm volatile("cp.async.wait_group 2;" ::: "memory")

__device__ __forceinline__ void ldsm4(uint32_t addr, uint32_t& r0, uint32_t& r1, uint32_t& r2, uint32_t& r3) {
    asm volatile("ldmatrix.sync.aligned.m8n8.x4.shared.b16 {%0,%1,%2,%3}, [%4];"
                 : "=r"(r0), "=r"(r1), "=r"(r2), "=r"(r3) : "r"(addr));
}
__device__ __forceinline__ void mma16816(float* c, const uint32_t* a, const uint32_t* b) {
    asm("mma.sync.aligned.m16n8k16.row.col.f32.f16.f16.f32 "
        "{%0,%1,%2,%3}, {%4,%5,%6,%7}, {%8,%9}, {%0,%1,%2,%3};"
        : "+f"(c[0]), "+f"(c[1]), "+f"(c[2]), "+f"(c[3])
        : "r"(a[0]), "r"(a[1]), "r"(a[2]), "r"(a[3]), "r"(b[0]), "r"(b[1]));
}
__device__ __forceinline__ float sigmoidf_(float x) { return 1.0f / (1.0f + __expf(-x)); }

// swizzled byte offset within an Nx64B tile: row r, 16B chunk c (0..3)
__device__ __forceinline__ uint32_t swz(int r, int c) {
    return (uint32_t)(r * 64 + ((c ^ ((r >> 1) & 3)) << 4));
}

// ---------------- single-pass fp16 HMMA GEMM (+ fused LSTM cell) ----------------
// D = A @ W^T + bias, A/W quantized fp16.
// A operand per chunk: chunk < xchunks -> Ax (ldax), else Ah (HDIM ld, k rebased).
// mode 0 (gates): gate-permuted output; epilogue applies LSTM cell, updates cstate,
//                 writes h (fp16) into hw [MROWS x HDIM]
// mode 1 (cls):   writes Co (ld DSTEPS*FDIM) and fp16 copy to ox [MROWS x FDIM]
__global__ void __launch_bounds__(NTHR, 2)
gemm_hmma(const __half* __restrict__ Ax, int ldax,
          const __half* __restrict__ Ah, int xchunks,
          const __half* __restrict__ W, int ldw,
          int K,
          const float* __restrict__ bias,
          float* __restrict__ cstate,
          float* __restrict__ Co,
          __half* __restrict__ ox,
          __half* __restrict__ hw,
          int mode, int first)
{
    extern __shared__ char smem[];
    const uint32_t sb = smem_u32(smem);
    const int tid = threadIdx.x;
    const int lane = tid & 31;
    const int wid = tid >> 5;
    const int wm = wid & 1;        // 0..1 -> 64-row slice
    const int wn = wid >> 1;       // 0..3 -> 32-col slice
    const int bm = blockIdx.y, bn = blockIdx.x;
    const int nch = K / BK;

    // loader precompute: each thread owns granule (tid) and (tid+256) per tile.
    const int r0g = tid >> 2, c0g = tid & 3;
    const uint32_t dOff = swz(r0g, c0g);              // +4096 for rows 64..127
    const size_t ldxb = (size_t)ldax * 2;
    const size_t ldhb = (size_t)HDIM * 2;
    const size_t ldwb = (size_t)ldw * 2;
    const char* pX = (const char*)Ax + (size_t)(bm * BM + r0g) * ldxb + c0g * 16;
    const char* pH = Ah ? (const char*)Ah + (size_t)(bm * BM + r0g) * ldhb + c0g * 16 : nullptr;
    const char* pW = (const char*)W + (size_t)(bn * BN + r0g) * ldwb + c0g * 16;
    const size_t ldx64 = ldxb * 64, ldh64 = ldhb * 64, ldw64 = ldwb * 64;

    auto load_stage = [&](int slot, int chunk) {
        const uint32_t stg = sb + slot * STAGE_B;
        const bool useH = (chunk >= xchunks);
        const char* a = useH ? pH : pX;
        const size_t lda64 = useH ? ldh64 : ldx64;
        const size_t kba = (size_t)(useH ? (chunk - xchunks) : chunk) * 64;
        const size_t kbw = (size_t)chunk * 64;
        cp16(stg + dOff,                a + kba);
        cp16(stg + dOff + 4096,         a + kba + lda64);
        cp16(stg + TILE_B + dOff,        pW + kbw);
        cp16(stg + TILE_B + dOff + 4096, pW + kbw + ldw64);
    };

    float acc[4][4][4];
#pragma unroll
    for (int mt = 0; mt < 4; mt++)
#pragma unroll
        for (int nt = 0; nt < 4; nt++)
#pragma unroll
            for (int e = 0; e < 4; e++) acc[mt][nt][e] = 0.0f;

    load_stage(0, 0); CP_COMMIT();
    load_stage(1, 1); CP_COMMIT();
    load_stage(2, 2); CP_COMMIT();

    const int lrow = lane & 15;
    const int lchk = lane >> 4;

    // loop-invariant swizzled ldmatrix offsets per kh half
    uint32_t offA[2][4], offW[2][2];
#pragma unroll
    for (int kh = 0; kh < 2; kh++) {
        const int cc = kh * 2 + lchk;
#pragma unroll
        for (int mt = 0; mt < 4; mt++)
            offA[kh][mt] = swz(wm * 64 + mt * 16 + lrow, cc);
#pragma unroll
        for (int np = 0; np < 2; np++)
            offW[kh][np] = swz(wn * 32 + np * 16 + lrow, cc);
    }

    for (int i = 0; i < nch; i++) {
        CP_WAIT2();
        __syncthreads();
        if (i + 3 < nch) load_stage((i + 3) % STAGES, i + 3);
        CP_COMMIT();

        const uint32_t stg = sb + (i % STAGES) * STAGE_B;
        const uint32_t sA = stg;
        const uint32_t sW = stg + TILE_B;

#pragma unroll
        for (int kh = 0; kh < 2; kh++) {
            uint32_t b[4][2], a[4][4];
#pragma unroll
            for (int np = 0; np < 2; np++) {
                uint32_t r0, r1, r2, r3;
                ldsm4(sW + offW[kh][np], r0, r1, r2, r3);
                b[np * 2][0] = r0; b[np * 2 + 1][0] = r1;
                b[np * 2][1] = r2; b[np * 2 + 1][1] = r3;
            }
#pragma unroll
            for (int mt = 0; mt < 4; mt++)
                ldsm4(sA + offA[kh][mt], a[mt][0], a[mt][1], a[mt][2], a[mt][3]);
#pragma unroll
            for (int mt = 0; mt < 4; mt++)
#pragma unroll
                for (int nt = 0; nt < 4; nt++)
                    mma16816(acc[mt][nt], a[mt], b[nt]);
        }
        __syncthreads();
    }

    // ---------------- epilogue ----------------
    const int rbase = bm * BM + wm * 64;
    const int cbase = bn * BN + wn * 32;
    const int qr = lane >> 2;            // 0..7
    const int qc = (lane & 3) * 2;       // 0,2,4,6

    if (mode == 0) {
        // gate-permuted columns: p = j*4 + gate (i,f,g,o). Even lane holds (p,p+1)=(i,f),
        // odd partner holds (p+2,p+3)=(g,o); shfl_xor(1) assembles the quad.
#pragma unroll
        for (int mt = 0; mt < 4; mt++) {
#pragma unroll
            for (int nt = 0; nt < 4; nt++) {
                const int p = cbase + nt * 8 + qc;
                const float bv0 = bias[p], bv1 = bias[p + 1];
                const float v0 = acc[mt][nt][0] + bv0;
                const float v1 = acc[mt][nt][1] + bv1;
                const float v2 = acc[mt][nt][2] + bv0;
                const float v3 = acc[mt][nt][3] + bv1;
                const float x0 = __shfl_xor_sync(0xffffffffu, v0, 1);
                const float x1 = __shfl_xor_sync(0xffffffffu, v1, 1);
                const float x2 = __shfl_xor_sync(0xffffffffu, v2, 1);
                const float x3 = __shfl_xor_sync(0xffffffffu, v3, 1);
                if (!(lane & 1)) {
                    const int j = p >> 2;            // hidden unit
                    const int r0 = rbase + mt * 16 + qr;
#pragma unroll
                    for (int half = 0; half < 2; half++) {
                        const int row = r0 + half * 8;
                        const float iv = half ? v2 : v0;
                        const float fv = half ? v3 : v1;
                        const float gv = half ? x2 : x0;
                        const float ov = half ? x3 : x1;
                        const float cold = first ? 0.0f : cstate[(size_t)row * HDIM + j];
                        const float cn = sigmoidf_(fv) * cold + sigmoidf_(iv) * tanhf(gv);
                        cstate[(size_t)row * HDIM + j] = cn;
                        const float h = sigmoidf_(ov) * tanhf(cn);
                        hw[(size_t)row * HDIM + j] = __float2half(h);
                    }
                }
            }
        }
    } else {
#pragma unroll
        for (int mt = 0; mt < 4; mt++) {
#pragma unroll
            for (int nt = 0; nt < 4; nt++) {
                const int col = cbase + nt * 8 + qc;
                const float bv0 = bias[col], bv1 = bias[col + 1];
#pragma unroll
                for (int half = 0; half < 2; half++) {
                    const int row = rbase + mt * 16 + qr + half * 8;
                    const float v0 = acc[mt][nt][half * 2 + 0] + bv0;
                    const float v1 = acc[mt][nt][half * 2 + 1] + bv1;
                    *(float2*)(Co + (size_t)row * (DSTEPS * FDIM) + col) = make_float2(v0, v1);
                    *(__half2*)(ox + (size_t)row * FDIM + col) =
                        __halves2half2(__float2half(v0), __float2half(v1));
                }
            }
        }
    }
}

// ---------------- elementwise prep kernels ----------------
__global__ void split_act(const float* __restrict__ x, __half* __restrict__ o)
{
    const int idx = blockIdx.x * blockDim.x + threadIdx.x;   // MROWS*FDIM
    o[idx] = __float2half(x[idx]);
}

// gates weights gate-permuted fp16: output row p = j*4 + gate, src row = gate*H + j
__global__ void split_weights(const float* __restrict__ W_ih, const float* __restrict__ W_hh,
                              const float* __restrict__ W_cls,
                              const float* __restrict__ b_ih, const float* __restrict__ b_hh,
                              __half* __restrict__ wg, __half* __restrict__ wc,
                              float* __restrict__ biasg)
{
    const int idx = blockIdx.x * blockDim.x + threadIdx.x;
    const int NG = GDIM * KFUSE;
    if (idx < NG) {
        const int p = idx / KFUSE, col = idx - p * KFUSE;
        const int src_n = (p & 3) * HDIM + (p >> 2);
        const float v = (col < FDIM) ? W_ih[(size_t)src_n * FDIM + col]
                                     : W_hh[(size_t)src_n * HDIM + (col - FDIM)];
        wg[idx] = __float2half(v);
        if (idx < GDIM) {
            const int sn = (idx & 3) * HDIM + (idx >> 2);
            biasg[idx] = b_ih[sn] + b_hh[sn];
        }
    } else {
        const int i2 = idx - NG;                // FDIM*HDIM
        wc[i2] = __float2half(W_cls[i2]);
    }
}

// ---------------- launch ----------------
extern "C" void kernel_launch(void* const* d_in, const int* in_sizes, int n_in,
                              void* d_out, int out_size)
{
    const float* x     = (const float*)d_in[0];
    const float* W_ih  = (const float*)d_in[1];
    const float* W_hh  = (const float*)d_in[2];
    const float* b_ih  = (const float*)d_in[3];
    const float* b_hh  = (const float*)d_in[4];
    const float* W_cls = (const float*)d_in[5];
    const float* b_cls = (const float*)d_in[6];
    float* out = (float*)d_out;                    // [8192 rows, 8 steps, 1024]

    __half *p_o, *p_wg, *p_wc;
    __half *p_h[2];
    float *p_biasg, *p_c;
    cudaGetSymbolAddress((void**)&p_o, g_out);
    {
        __half* base;
        cudaGetSymbolAddress((void**)&base, g_h);
        p_h[0] = base; p_h[1] = base + (size_t)MROWS * HDIM;
    }
    cudaGetSymbolAddress((void**)&p_wg, g_wg);
    cudaGetSymbolAddress((void**)&p_wc, g_wc);
    cudaGetSymbolAddress((void**)&p_biasg, g_biasg);
    cudaGetSymbolAddress((void**)&p_c, g_c);

    cudaFuncSetAttribute(gemm_hmma, cudaFuncAttributeMaxDynamicSharedMemorySize, SMEM_TOTAL);

    split_act<<<(MROWS * FDIM) / 256, 256>>>(x, p_o);
    split_weights<<<(GDIM * KFUSE + FDIM * HDIM) / 256, 256>>>(W_ih, W_hh, W_cls, b_ih, b_hh,
                                                               p_wg, p_wc, p_biasg);

    const dim3 gridG(GDIM / BN, MROWS / BM);   // (16, 64)
    const dim3 gridC(FDIM / BN, MROWS / BM);   // (8, 64)

    for (int d = 0; d < DSTEPS; d++) {
        const int wb = d & 1;                 // h write buffer
        const int rb = (d + 1) & 1;           // h read buffer (prev step)
        // gates GEMM + fused LSTM cell. Step 0: K=1024 (h0 == 0, skip h chunks).
        const int Kg = (d == 0) ? FDIM : KFUSE;
        gemm_hmma<<<gridG, NTHR, SMEM_TOTAL>>>(p_o, FDIM,
                                               p_h[rb], FDIM / BK,
                                               p_wg, KFUSE,
                                               Kg, p_biasg,
                                               p_c, nullptr,
                                               nullptr,
                                               p_h[wb],
                                               0, d == 0 ? 1 : 0);
        // out = h @ W_cls^T + b_cls -> d_out slice d; fp16 copy into out buffer
        gemm_hmma<<<gridC, NTHR, SMEM_TOTAL>>>(p_h[wb], HDIM,
                                               nullptr, 1 << 30,
                                               p_wc, HDIM,
                                               HDIM, b_cls,
                                               nullptr, out + (size_t)d * FDIM,
                                               p_o,
                                               nullptr,
                                               1, 0);
    }
}

// round 10
// speedup vs baseline: 2.4726x; 1.0834x over previous
#include <cuda_runtime.h>
#include <cuda_fp16.h>
#include <cstdint>
#include <cstddef>

// ---------------- problem constants ----------------
#define MROWS 8192
#define FDIM  1024
#define HDIM  512
#define GDIM  2048
#define KFUSE 1536
#define DSTEPS 8

// ---------------- GEMM tile config ----------------
#define BM 128
#define BN 64
#define BK 32                 // fp16 elems per chunk (64 bytes per row)
#define STAGES 4
#define NTHR 256
#define A_TILE_B (BM*64)      // 8192
#define W_TILE_B (BN*64)      // 4096
#define STAGE_B (A_TILE_B + W_TILE_B)    // 12288
#define SMEM_TOTAL (STAGES*STAGE_B)      // 49152

// ---------------- scratch (device globals) ----------------
__device__ __align__(256) __half g_out[(size_t)MROWS*FDIM];     // x-part of A (cls output)
__device__ __align__(256) __half g_h[2][(size_t)MROWS*HDIM];    // double-buffered h
__device__ __align__(256) __half g_wg[(size_t)GDIM*KFUSE];      // gate-permuted fused W (fp16)
__device__ __align__(256) __half g_wc[(size_t)FDIM*HDIM];       // W_cls (fp16)
__device__ __align__(256) float g_biasg[GDIM];                  // permuted b_ih+b_hh
__device__ __align__(256) float g_c[(size_t)MROWS*HDIM];

// ---------------- helpers ----------------
__device__ __forceinline__ uint32_t smem_u32(const void* p) {
    uint32_t a;
    asm("{ .reg .u64 t; cvta.to.shared.u64 t, %1; cvt.u32.u64 %0, t; }" : "=r"(a) : "l"(p));
    return a;
}
__device__ __forceinline__ void cp16(uint32_t dst, const void* src) {
    asm volatile("cp.async.cg.shared.global [%0], [%1], 16;" :: "r"(dst), "l"(src) : "memory");
}
#define CP_COMMIT() asm volatile("cp.async.commit_group;" ::: "memory")
#define CP_WAIT2()  asm volatile("cp.async.wait_group 2;" ::: "memory")

__device__ __forceinline__ void ldsm4(uint32_t addr, uint32_t& r0, uint32_t& r1, uint32_t& r2, uint32_t& r3) {
    asm volatile("ldmatrix.sync.aligned.m8n8.x4.shared.b16 {%0,%1,%2,%3}, [%4];"
                 : "=r"(r0), "=r"(r1), "=r"(r2), "=r"(r3) : "r"(addr));
}
__device__ __forceinline__ void mma16816(float* c, const uint32_t* a, const uint32_t* b) {
    asm("mma.sync.aligned.m16n8k16.row.col.f32.f16.f16.f32 "
        "{%0,%1,%2,%3}, {%4,%5,%6,%7}, {%8,%9}, {%0,%1,%2,%3};"
        : "+f"(c[0]), "+f"(c[1]), "+f"(c[2]), "+f"(c[3])
        : "r"(a[0]), "r"(a[1]), "r"(a[2]), "r"(a[3]), "r"(b[0]), "r"(b[1]));
}
__device__ __forceinline__ float sigmoidf_(float x) { return 1.0f / (1.0f + __expf(-x)); }

// swizzled byte offset within an Nx64B tile: row r, 16B chunk c (0..3)
__device__ __forceinline__ uint32_t swz(int r, int c) {
    return (uint32_t)(r * 64 + ((c ^ ((r >> 1) & 3)) << 4));
}

// ---------------- single-pass fp16 HMMA GEMM (+ fused LSTM cell) ----------------
// CTA tile 128x64, 8 warps of 32x32, 3 CTAs/SM target.
// A operand per chunk: chunk < xchunks -> Ax (ldax), else Ah (HDIM ld, k rebased).
// mode 0 (gates): gate-permuted output; epilogue applies LSTM cell, updates cstate,
//                 writes h (fp16) into hw [MROWS x HDIM]
// mode 1 (cls):   writes Co (ld DSTEPS*FDIM) and fp16 copy to ox [MROWS x FDIM]
__global__ void __launch_bounds__(NTHR, 3)
gemm_hmma(const __half* __restrict__ Ax, int ldax,
          const __half* __restrict__ Ah, int xchunks,
          const __half* __restrict__ W, int ldw,
          int K,
          const float* __restrict__ bias,
          float* __restrict__ cstate,
          float* __restrict__ Co,
          __half* __restrict__ ox,
          __half* __restrict__ hw,
          int mode, int first)
{
    extern __shared__ char smem[];
    const uint32_t sb = smem_u32(smem);
    const int tid = threadIdx.x;
    const int lane = tid & 31;
    const int wid = tid >> 5;
    const int wm = wid & 3;        // 0..3 -> 32-row slice
    const int wn = wid >> 2;       // 0..1 -> 32-col slice
    const int bm = blockIdx.y, bn = blockIdx.x;
    const int nch = K / BK;

    // loader precompute: granules g = tid (A rows 0..63), tid+256 (A rows 64..127),
    // tid+512 (W rows 0..63). dst swizzle reuses dOff (+4096 for A's 2nd half).
    const int r0g = tid >> 2, c0g = tid & 3;
    const uint32_t dOff = swz(r0g, c0g);
    const size_t ldxb = (size_t)ldax * 2;
    const size_t ldhb = (size_t)HDIM * 2;
    const size_t ldwb = (size_t)ldw * 2;
    const char* pX = (const char*)Ax + (size_t)(bm * BM + r0g) * ldxb + c0g * 16;
    const char* pH = Ah ? (const char*)Ah + (size_t)(bm * BM + r0g) * ldhb + c0g * 16 : nullptr;
    const char* pW = (const char*)W + (size_t)(bn * BN + r0g) * ldwb + c0g * 16;
    const size_t ldx64 = ldxb * 64, ldh64 = ldhb * 64;

    auto load_stage = [&](int slot, int chunk) {
        const uint32_t stg = sb + slot * STAGE_B;
        const bool useH = (chunk >= xchunks);
        const char* a = useH ? pH : pX;
        const size_t lda64 = useH ? ldh64 : ldx64;
        const size_t kba = (size_t)(useH ? (chunk - xchunks) : chunk) * 64;
        const size_t kbw = (size_t)chunk * 64;
        cp16(stg + dOff,               a + kba);
        cp16(stg + dOff + 4096,        a + kba + lda64);
        cp16(stg + A_TILE_B + dOff,    pW + kbw);
    };

    float acc[2][4][4];
#pragma unroll
    for (int mt = 0; mt < 2; mt++)
#pragma unroll
        for (int nt = 0; nt < 4; nt++)
#pragma unroll
            for (int e = 0; e < 4; e++) acc[mt][nt][e] = 0.0f;

    load_stage(0, 0); CP_COMMIT();
    load_stage(1, 1); CP_COMMIT();
    load_stage(2, 2); CP_COMMIT();

    const int lrow = lane & 15;
    const int lchk = lane >> 4;

    // loop-invariant swizzled ldmatrix offsets per kh half
    uint32_t offA[2][2], offW[2][2];
#pragma unroll
    for (int kh = 0; kh < 2; kh++) {
        const int cc = kh * 2 + lchk;
#pragma unroll
        for (int mt = 0; mt < 2; mt++)
            offA[kh][mt] = swz(wm * 32 + mt * 16 + lrow, cc);
#pragma unroll
        for (int np = 0; np < 2; np++)
            offW[kh][np] = swz(wn * 32 + np * 16 + lrow, cc);
    }

    for (int i = 0; i < nch; i++) {
        CP_WAIT2();
        __syncthreads();
        if (i + 3 < nch) load_stage((i + 3) % STAGES, i + 3);
        CP_COMMIT();

        const uint32_t stg = sb + (i % STAGES) * STAGE_B;
        const uint32_t sA = stg;
        const uint32_t sW = stg + A_TILE_B;

#pragma unroll
        for (int kh = 0; kh < 2; kh++) {
            uint32_t b[4][2], a[2][4];
#pragma unroll
            for (int np = 0; np < 2; np++) {
                uint32_t r0, r1, r2, r3;
                ldsm4(sW + offW[kh][np], r0, r1, r2, r3);
                b[np * 2][0] = r0; b[np * 2 + 1][0] = r1;
                b[np * 2][1] = r2; b[np * 2 + 1][1] = r3;
            }
#pragma unroll
            for (int mt = 0; mt < 2; mt++)
                ldsm4(sA + offA[kh][mt], a[mt][0], a[mt][1], a[mt][2], a[mt][3]);
#pragma unroll
            for (int mt = 0; mt < 2; mt++)
#pragma unroll
                for (int nt = 0; nt < 4; nt++)
                    mma16816(acc[mt][nt], a[mt], b[nt]);
        }
        __syncthreads();
    }

    // ---------------- epilogue ----------------
    const int rbase = bm * BM + wm * 32;
    const int cbase = bn * BN + wn * 32;
    const int qr = lane >> 2;            // 0..7
    const int qc = (lane & 3) * 2;       // 0,2,4,6

    if (mode == 0) {
        // gate-permuted columns: p = j*4 + gate (i,f,g,o). Even lane holds (p,p+1)=(i,f),
        // odd partner holds (p+2,p+3)=(g,o); shfl_xor(1) assembles the quad.
#pragma unroll
        for (int mt = 0; mt < 2; mt++) {
#pragma unroll
            for (int nt = 0; nt < 4; nt++) {
                const int p = cbase + nt * 8 + qc;
                const float bv0 = bias[p], bv1 = bias[p + 1];
                const float v0 = acc[mt][nt][0] + bv0;
                const float v1 = acc[mt][nt][1] + bv1;
                const float v2 = acc[mt][nt][2] + bv0;
                const float v3 = acc[mt][nt][3] + bv1;
                const float x0 = __shfl_xor_sync(0xffffffffu, v0, 1);
                const float x1 = __shfl_xor_sync(0xffffffffu, v1, 1);
                const float x2 = __shfl_xor_sync(0xffffffffu, v2, 1);
                const float x3 = __shfl_xor_sync(0xffffffffu, v3, 1);
                if (!(lane & 1)) {
                    const int j = p >> 2;            // hidden unit
                    const int r0 = rbase + mt * 16 + qr;
#pragma unroll
                    for (int half = 0; half < 2; half++) {
                        const int row = r0 + half * 8;
                        const float iv = half ? v2 : v0;
                        const float fv = half ? v3 : v1;
                        const float gv = half ? x2 : x0;
                        const float ov = half ? x3 : x1;
                        const float cold = first ? 0.0f : cstate[(size_t)row * HDIM + j];
                        const float cn = sigmoidf_(fv) * cold + sigmoidf_(iv) * tanhf(gv);
                        cstate[(size_t)row * HDIM + j] = cn;
                        const float h = sigmoidf_(ov) * tanhf(cn);
                        hw[(size_t)row * HDIM + j] = __float2half(h);
                    }
                }
            }
        }
    } else {
#pragma unroll
        for (int mt = 0; mt < 2; mt++) {
#pragma unroll
            for (int nt = 0; nt < 4; nt++) {
                const int col = cbase + nt * 8 + qc;
                const float bv0 = bias[col], bv1 = bias[col + 1];
#pragma unroll
                for (int half = 0; half < 2; half++) {
                    const int row = rbase + mt * 16 + qr + half * 8;
                    const float v0 = acc[mt][nt][half * 2 + 0] + bv0;
                    const float v1 = acc[mt][nt][half * 2 + 1] + bv1;
                    *(float2*)(Co + (size_t)row * (DSTEPS * FDIM) + col) = make_float2(v0, v1);
                    *(__half2*)(ox + (size_t)row * FDIM + col) =
                        __halves2half2(__float2half(v0), __float2half(v1));
                }
            }
        }
    }
}

// ---------------- elementwise prep kernels ----------------
__global__ void split_act(const float* __restrict__ x, __half* __restrict__ o)
{
    const int idx = blockIdx.x * blockDim.x + threadIdx.x;   // MROWS*FDIM
    o[idx] = __float2half(x[idx]);
}

// gates weights gate-permuted fp16: output row p = j*4 + gate, src row = gate*H + j
__global__ void split_weights(const float* __restrict__ W_ih, const float* __restrict__ W_hh,
                              const float* __restrict__ W_cls,
                              const float* __restrict__ b_ih, const float* __restrict__ b_hh,
                              __half* __restrict__ wg, __half* __restrict__ wc,
                              float* __restrict__ biasg)
{
    const int idx = blockIdx.x * blockDim.x + threadIdx.x;
    const int NG = GDIM * KFUSE;
    if (idx < NG) {
        const int p = idx / KFUSE, col = idx - p * KFUSE;
        const int src_n = (p & 3) * HDIM + (p >> 2);
        const float v = (col < FDIM) ? W_ih[(size_t)src_n * FDIM + col]
                                     : W_hh[(size_t)src_n * HDIM + (col - FDIM)];
        wg[idx] = __float2half(v);
        if (idx < GDIM) {
            const int sn = (idx & 3) * HDIM + (idx >> 2);
            biasg[idx] = b_ih[sn] + b_hh[sn];
        }
    } else {
        const int i2 = idx - NG;                // FDIM*HDIM
        wc[i2] = __float2half(W_cls[i2]);
    }
}

// ---------------- launch ----------------
extern "C" void kernel_launch(void* const* d_in, const int* in_sizes, int n_in,
                              void* d_out, int out_size)
{
    const float* x     = (const float*)d_in[0];
    const float* W_ih  = (const float*)d_in[1];
    const float* W_hh  = (const float*)d_in[2];
    const float* b_ih  = (const float*)d_in[3];
    const float* b_hh  = (const float*)d_in[4];
    const float* W_cls = (const float*)d_in[5];
    const float* b_cls = (const float*)d_in[6];
    float* out = (float*)d_out;                    // [8192 rows, 8 steps, 1024]

    __half *p_o, *p_wg, *p_wc;
    __half *p_h[2];
    float *p_biasg, *p_c;
    cudaGetSymbolAddress((void**)&p_o, g_out);
    {
        __half* base;
        cudaGetSymbolAddress((void**)&base, g_h);
        p_h[0] = base; p_h[1] = base + (size_t)MROWS * HDIM;
    }
    cudaGetSymbolAddress((void**)&p_wg, g_wg);
    cudaGetSymbolAddress((void**)&p_wc, g_wc);
    cudaGetSymbolAddress((void**)&p_biasg, g_biasg);
    cudaGetSymbolAddress((void**)&p_c, g_c);

    cudaFuncSetAttribute(gemm_hmma, cudaFuncAttributeMaxDynamicSharedMemorySize, SMEM_TOTAL);

    split_act<<<(MROWS * FDIM) / 256, 256>>>(x, p_o);
    split_weights<<<(GDIM * KFUSE + FDIM * HDIM) / 256, 256>>>(W_ih, W_hh, W_cls, b_ih, b_hh,
                                                               p_wg, p_wc, p_biasg);

    const dim3 gridG(GDIM / BN, MROWS / BM);   // (32, 64)
    const dim3 gridC(FDIM / BN, MROWS / BM);   // (16, 64)

    for (int d = 0; d < DSTEPS; d++) {
        const int wb = d & 1;                 // h write buffer
        const int rb = (d + 1) & 1;           // h read buffer (prev step)
        // gates GEMM + fused LSTM cell. Step 0: K=1024 (h0 == 0, skip h chunks).
        const int Kg = (d == 0) ? FDIM : KFUSE;
        gemm_hmma<<<gridG, NTHR, SMEM_TOTAL>>>(p_o, FDIM,
                                               p_h[rb], FDIM / BK,
                                               p_wg, KFUSE,
                                               Kg, p_biasg,
                                               p_c, nullptr,
                                               nullptr,
                                               p_h[wb],
                                               0, d == 0 ? 1 : 0);
        // out = h @ W_cls^T + b_cls -> d_out slice d; fp16 copy into out buffer
        gemm_hmma<<<gridC, NTHR, SMEM_TOTAL>>>(p_h[wb], HDIM,
                                               nullptr, 1 << 30,
                                               p_wc, HDIM,
                                               HDIM, b_cls,
                                               nullptr, out + (size_t)d * FDIM,
                                               p_o,
                                               nullptr,
                                               1, 0);
    }
}